// round 1
// baseline (speedup 1.0000x reference)
#include <cuda_runtime.h>
#include <math.h>

// Problem dims (fixed by the dataset)
#define B_   8
#define N_   8192
#define D_   512
#define H_   8
#define DK_  64
#define DV_  64
#define BN_ROWS (B_ * N_)   // 65536

// ---------------- scratch (static device arrays; no allocation) ----------------
__device__ float g_q[(size_t)BN_ROWS * D_];                 // 134 MB
__device__ float g_k[(size_t)BN_ROWS * D_];                 // 134 MB
__device__ float g_v[(size_t)BN_ROWS * D_];                 // 134 MB
__device__ float g_qinv[(size_t)BN_ROWS * H_];              // 2 MB : gamma[h]/||q_row_head||
__device__ float g_kvp[(size_t)64 * 8 * 64 * 64];           // 8.4 MB: partial kv [bh][chunk][dk][dv]
__device__ float g_M[(size_t)B_ * D_ * D_];                 // 8.4 MB: folded kv_n @ Wo per batch

// =====================================================================
// Kernel 1: QKV projection. C = X @ W + bias for W in {Wq, Wk, Wv}.
// 128x128x8 tile, 256 threads, 8x8 register tile per thread.
// grid = (512/128, 65536/128, 3)
// =====================================================================
__global__ __launch_bounds__(256) void qkv_gemm_kernel(
    const float* __restrict__ X,
    const float* __restrict__ Wq, const float* __restrict__ Wk, const float* __restrict__ Wv,
    const float* __restrict__ bq, const float* __restrict__ bk, const float* __restrict__ bv)
{
    const float* W; const float* bias; float* C;
    if (blockIdx.z == 0)      { W = Wq; bias = bq; C = g_q; }
    else if (blockIdx.z == 1) { W = Wk; bias = bk; C = g_k; }
    else                      { W = Wv; bias = bv; C = g_v; }

    __shared__ float As[8][132];   // [k][m], padded
    __shared__ float Bs[8][128];   // [k][n]

    const int tid = threadIdx.x;
    const int m0 = blockIdx.y * 128;
    const int n0 = blockIdx.x * 128;

    const int ar  = tid >> 1;          // A load row   0..127
    const int ac4 = (tid & 1) << 2;    // A load col4  0 or 4
    const int bkr = tid >> 5;          // B load k-row 0..7
    const int bc4 = (tid & 31) << 2;   // B load col4  0..124

    const int tx = tid & 15;           // col micro 0..15
    const int ty = tid >> 4;           // row micro 0..15

    float acc[8][8];
    #pragma unroll
    for (int i = 0; i < 8; i++)
        #pragma unroll
        for (int j = 0; j < 8; j++) acc[i][j] = 0.f;

    for (int k0 = 0; k0 < D_; k0 += 8) {
        float4 av = *reinterpret_cast<const float4*>(&X[(size_t)(m0 + ar) * D_ + k0 + ac4]);
        As[ac4 + 0][ar] = av.x;
        As[ac4 + 1][ar] = av.y;
        As[ac4 + 2][ar] = av.z;
        As[ac4 + 3][ar] = av.w;
        float4 wv = *reinterpret_cast<const float4*>(&W[(size_t)(k0 + bkr) * D_ + n0 + bc4]);
        *reinterpret_cast<float4*>(&Bs[bkr][bc4]) = wv;
        __syncthreads();

        #pragma unroll
        for (int kk = 0; kk < 8; kk++) {
            float4 a0 = *reinterpret_cast<const float4*>(&As[kk][ty * 8]);
            float4 a1 = *reinterpret_cast<const float4*>(&As[kk][ty * 8 + 4]);
            float4 b0 = *reinterpret_cast<const float4*>(&Bs[kk][tx * 8]);
            float4 b1 = *reinterpret_cast<const float4*>(&Bs[kk][tx * 8 + 4]);
            float a[8] = {a0.x, a0.y, a0.z, a0.w, a1.x, a1.y, a1.z, a1.w};
            float b[8] = {b0.x, b0.y, b0.z, b0.w, b1.x, b1.y, b1.z, b1.w};
            #pragma unroll
            for (int i = 0; i < 8; i++)
                #pragma unroll
                for (int j = 0; j < 8; j++) acc[i][j] = fmaf(a[i], b[j], acc[i][j]);
        }
        __syncthreads();
    }

    #pragma unroll
    for (int i = 0; i < 8; i++) {
        const size_t row = (size_t)(m0 + ty * 8 + i);
        #pragma unroll
        for (int j = 0; j < 8; j += 4) {
            const int col = n0 + tx * 8 + j;
            float4 o;
            o.x = acc[i][j + 0] + bias[col + 0];
            o.y = acc[i][j + 1] + bias[col + 1];
            o.z = acc[i][j + 2] + bias[col + 2];
            o.w = acc[i][j + 3] + bias[col + 3];
            *reinterpret_cast<float4*>(&C[row * D_ + col]) = o;
        }
    }
}

// =====================================================================
// Kernel 2: per-(row, head) inverse norms of q: gamma[h] / ||q[row, h*64 : h*64+64]||
// One warp per row; lanes grouped 4 per head.
// grid = 65536/8 = 8192, block = 256 (8 warps)
// =====================================================================
__global__ __launch_bounds__(256) void qinv_kernel(const float* __restrict__ gamma)
{
    const int warp = threadIdx.x >> 5;
    const int lane = threadIdx.x & 31;
    const int row  = blockIdx.x * 8 + warp;
    const int h    = lane >> 2;      // 0..7
    const int sub  = lane & 3;       // 0..3

    const float* qr = g_q + (size_t)row * D_ + h * 64 + sub;
    float s = 0.f;
    #pragma unroll
    for (int j = 0; j < 16; j++) { float x = qr[j * 4]; s = fmaf(x, x, s); }
    s += __shfl_xor_sync(0xffffffffu, s, 1);
    s += __shfl_xor_sync(0xffffffffu, s, 2);
    if (sub == 0) g_qinv[(size_t)row * H_ + h] = gamma[h] / sqrtf(s);
}

// =====================================================================
// Kernel 3: partial kv[dk][dv] = sum_n k[b,n,h,dk]*v[b,n,h,dv] over an N-chunk.
// grid = (8 chunks, 64 bh), block = 256, 4x4 register tile per thread.
// =====================================================================
__global__ __launch_bounds__(256) void kv_partial_kernel()
{
    const int chunk = blockIdx.x;        // 0..7 (1024 rows each)
    const int bh    = blockIdx.y;        // 0..63
    const int b     = bh >> 3;
    const int h     = bh & 7;

    __shared__ float ks[16][68];
    __shared__ float vs[16][68];

    const int tid = threadIdx.x;
    const int lr  = tid >> 4;            // 0..15 row within tile
    const int lc4 = (tid & 15) << 2;     // 0..60
    const int tx  = tid & 15;
    const int ty  = tid >> 4;

    float acc[4][4];
    #pragma unroll
    for (int i = 0; i < 4; i++)
        #pragma unroll
        for (int j = 0; j < 4; j++) acc[i][j] = 0.f;

    const size_t base = (size_t)b * N_ * D_ + h * 64;

    const int nbeg = chunk * 1024;
    for (int n0 = nbeg; n0 < nbeg + 1024; n0 += 16) {
        const size_t off = base + (size_t)(n0 + lr) * D_ + lc4;
        *reinterpret_cast<float4*>(&ks[lr][lc4]) = *reinterpret_cast<const float4*>(&g_k[off]);
        *reinterpret_cast<float4*>(&vs[lr][lc4]) = *reinterpret_cast<const float4*>(&g_v[off]);
        __syncthreads();
        #pragma unroll
        for (int nn = 0; nn < 16; nn++) {
            float a[4], w[4];
            #pragma unroll
            for (int i = 0; i < 4; i++) a[i] = ks[nn][ty * 4 + i];
            #pragma unroll
            for (int j = 0; j < 4; j++) w[j] = vs[nn][tx * 4 + j];
            #pragma unroll
            for (int i = 0; i < 4; i++)
                #pragma unroll
                for (int j = 0; j < 4; j++) acc[i][j] = fmaf(a[i], w[j], acc[i][j]);
        }
        __syncthreads();
    }

    float* P = g_kvp + ((size_t)bh * 8 + chunk) * 4096;
    #pragma unroll
    for (int i = 0; i < 4; i++) {
        float4 o = make_float4(acc[i][0], acc[i][1], acc[i][2], acc[i][3]);
        *reinterpret_cast<float4*>(&P[(ty * 4 + i) * 64 + tx * 4]) = o;
    }
}

// =====================================================================
// Kernel 4: reduce kv partials, normalize rows (gamma[h]/||kv[dk,:]||),
// and fold into M[b][h*64+dk][d] = sum_dv kv_n[dk][dv] * Wo[h*64+dv][d].
// grid = 64 (bh), block = 256.
// =====================================================================
__global__ __launch_bounds__(256) void kv_reduce_M_kernel(
    const float* __restrict__ Wo, const float* __restrict__ gamma)
{
    const int bh = blockIdx.x;
    const int b  = bh >> 3;
    const int h  = bh & 7;

    __shared__ float kvs[64][65];
    __shared__ float wos[64][65];
    __shared__ float rs[64];

    const int tid = threadIdx.x;

    // reduce 8 partials
    for (int idx = tid; idx < 4096; idx += 256) {
        float s = 0.f;
        #pragma unroll
        for (int p = 0; p < 8; p++) s += g_kvp[((size_t)bh * 8 + p) * 4096 + idx];
        kvs[idx >> 6][idx & 63] = s;
    }
    __syncthreads();

    // row scales
    if (tid < 64) {
        float s = 0.f;
        #pragma unroll
        for (int c = 0; c < 64; c++) { float x = kvs[tid][c]; s = fmaf(x, x, s); }
        rs[tid] = gamma[h] / sqrtf(s);
    }
    __syncthreads();

    const int tx = tid & 15;   // d micro
    const int ty = tid >> 4;   // dk micro

    for (int dt = 0; dt < 8; dt++) {
        const int d0 = dt * 64;
        for (int idx = tid; idx < 4096; idx += 256) {
            const int dv = idx >> 6, dd = idx & 63;
            wos[dv][dd] = Wo[(size_t)(h * 64 + dv) * D_ + d0 + dd];
        }
        __syncthreads();

        float acc[4][4];
        #pragma unroll
        for (int i = 0; i < 4; i++)
            #pragma unroll
            for (int j = 0; j < 4; j++) acc[i][j] = 0.f;

        #pragma unroll 8
        for (int dv = 0; dv < 64; dv++) {
            float a[4], w[4];
            #pragma unroll
            for (int i = 0; i < 4; i++) a[i] = kvs[ty * 4 + i][dv];
            #pragma unroll
            for (int j = 0; j < 4; j++) w[j] = wos[dv][tx * 4 + j];
            #pragma unroll
            for (int i = 0; i < 4; i++)
                #pragma unroll
                for (int j = 0; j < 4; j++) acc[i][j] = fmaf(a[i], w[j], acc[i][j]);
        }

        #pragma unroll
        for (int i = 0; i < 4; i++) {
            const float sc = rs[ty * 4 + i];
            float* mp = &g_M[(size_t)b * D_ * D_ + (size_t)(h * 64 + ty * 4 + i) * D_ + d0 + tx * 4];
            float4 o = make_float4(acc[i][0] * sc, acc[i][1] * sc, acc[i][2] * sc, acc[i][3] * sc);
            *reinterpret_cast<float4*>(mp) = o;
        }
        __syncthreads();
    }
}

// =====================================================================
// Kernel 5: final batched GEMM  y[b] = (q[b] * qinv) @ M[b] + bo
// Same tiling as kernel 1; A elements scaled by qinv[row, k/64] at load.
// grid = (512/128, 8192/128, 8 batches)
// =====================================================================
__global__ __launch_bounds__(256) void final_gemm_kernel(
    const float* __restrict__ bo, float* __restrict__ out)
{
    const int bz = blockIdx.z;
    const float* A  = g_q + (size_t)bz * N_ * D_;
    const float* Bm = g_M + (size_t)bz * D_ * D_;
    float* C        = out + (size_t)bz * N_ * D_;

    __shared__ float As[8][132];
    __shared__ float Bs[8][128];

    const int tid = threadIdx.x;
    const int m0 = blockIdx.y * 128;
    const int n0 = blockIdx.x * 128;

    const int ar  = tid >> 1;
    const int ac4 = (tid & 1) << 2;
    const int bkr = tid >> 5;
    const int bc4 = (tid & 31) << 2;
    const int tx = tid & 15;
    const int ty = tid >> 4;

    float acc[8][8];
    #pragma unroll
    for (int i = 0; i < 8; i++)
        #pragma unroll
        for (int j = 0; j < 8; j++) acc[i][j] = 0.f;

    const size_t ginvrow = ((size_t)bz * N_ + m0 + ar) * H_;

    for (int k0 = 0; k0 < D_; k0 += 8) {
        float4 av = *reinterpret_cast<const float4*>(&A[(size_t)(m0 + ar) * D_ + k0 + ac4]);
        const float s = g_qinv[ginvrow + ((k0 + ac4) >> 6)];
        As[ac4 + 0][ar] = av.x * s;
        As[ac4 + 1][ar] = av.y * s;
        As[ac4 + 2][ar] = av.z * s;
        As[ac4 + 3][ar] = av.w * s;
        float4 wv = *reinterpret_cast<const float4*>(&Bm[(size_t)(k0 + bkr) * D_ + n0 + bc4]);
        *reinterpret_cast<float4*>(&Bs[bkr][bc4]) = wv;
        __syncthreads();

        #pragma unroll
        for (int kk = 0; kk < 8; kk++) {
            float4 a0 = *reinterpret_cast<const float4*>(&As[kk][ty * 8]);
            float4 a1 = *reinterpret_cast<const float4*>(&As[kk][ty * 8 + 4]);
            float4 b0 = *reinterpret_cast<const float4*>(&Bs[kk][tx * 8]);
            float4 b1 = *reinterpret_cast<const float4*>(&Bs[kk][tx * 8 + 4]);
            float a[8] = {a0.x, a0.y, a0.z, a0.w, a1.x, a1.y, a1.z, a1.w};
            float b[8] = {b0.x, b0.y, b0.z, b0.w, b1.x, b1.y, b1.z, b1.w};
            #pragma unroll
            for (int i = 0; i < 8; i++)
                #pragma unroll
                for (int j = 0; j < 8; j++) acc[i][j] = fmaf(a[i], b[j], acc[i][j]);
        }
        __syncthreads();
    }

    #pragma unroll
    for (int i = 0; i < 8; i++) {
        const size_t row = (size_t)(m0 + ty * 8 + i);
        #pragma unroll
        for (int j = 0; j < 8; j += 4) {
            const int col = n0 + tx * 8 + j;
            float4 o;
            o.x = acc[i][j + 0] + bo[col + 0];
            o.y = acc[i][j + 1] + bo[col + 1];
            o.z = acc[i][j + 2] + bo[col + 2];
            o.w = acc[i][j + 3] + bo[col + 3];
            *reinterpret_cast<float4*>(&C[row * D_ + col]) = o;
        }
    }
}

// =====================================================================
extern "C" void kernel_launch(void* const* d_in, const int* in_sizes, int n_in,
                              void* d_out, int out_size)
{
    const float* X     = (const float*)d_in[0];
    const float* Wq    = (const float*)d_in[1];
    const float* bq    = (const float*)d_in[2];
    const float* Wk    = (const float*)d_in[3];
    const float* bk    = (const float*)d_in[4];
    const float* Wv    = (const float*)d_in[5];
    const float* bv    = (const float*)d_in[6];
    const float* Wo    = (const float*)d_in[7];
    const float* bo    = (const float*)d_in[8];
    const float* gamma = (const float*)d_in[9];
    float* out = (float*)d_out;

    // 1) q,k,v = X @ {Wq,Wk,Wv} + bias
    qkv_gemm_kernel<<<dim3(D_ / 128, BN_ROWS / 128, 3), 256>>>(X, Wq, Wk, Wv, bq, bk, bv);
    // 2) per-(row, head) q inverse norms
    qinv_kernel<<<BN_ROWS / 8, 256>>>(gamma);
    // 3) kv partial outer products
    kv_partial_kernel<<<dim3(8, 64), 256>>>();
    // 4) reduce kv, normalize, fold Wo -> M[b]
    kv_reduce_M_kernel<<<64, 256>>>(Wo, gamma);
    // 5) y[b] = q_n[b] @ M[b] + bo
    final_gemm_kernel<<<dim3(D_ / 128, N_ / 128, B_), 256>>>(bo, out);
}

// round 3
// speedup vs baseline: 2.3391x; 2.3391x over previous
#include <cuda_runtime.h>
#include <cuda_bf16.h>
#include <math.h>
#include <stdint.h>

#define B_   8
#define N_   8192
#define D_   512
#define H_   8
#define BN_ROWS 65536

// ---------------- scratch (static device arrays) ----------------
__device__ float g_qkv[(size_t)3 * BN_ROWS * D_];            // q | k | v fp32
__device__ __nv_bfloat16 g_Xh[(size_t)BN_ROWS * D_];
__device__ __nv_bfloat16 g_Xl[(size_t)BN_ROWS * D_];
__device__ __nv_bfloat16 g_qsh[(size_t)BN_ROWS * D_];        // q * qinv, split
__device__ __nv_bfloat16 g_qsl[(size_t)BN_ROWS * D_];
__device__ __nv_bfloat16 g_Bth[1536 * 512];                  // [n][k] Wq|Wk|Wv^T hi
__device__ __nv_bfloat16 g_Btl[1536 * 512];
__device__ float g_biasC[1536];
__device__ float g_kvp[(size_t)64 * 8 * 4096];
__device__ __nv_bfloat16 g_Mth[(size_t)B_ * 512 * 512];      // Mt[b][d][k] hi
__device__ __nv_bfloat16 g_Mtl[(size_t)B_ * 512 * 512];

// ---------------- helpers ----------------
__device__ __forceinline__ uint32_t smem_u32(const void* p) {
    uint32_t a;
    asm("{ .reg .u64 t; cvta.to.shared.u64 t, %1; cvt.u32.u64 %0, t; }" : "=r"(a) : "l"(p));
    return a;
}
__device__ __forceinline__ void ldsm4(uint32_t* r, uint32_t a) {
    asm volatile("ldmatrix.sync.aligned.m8n8.x4.shared.b16 {%0,%1,%2,%3}, [%4];"
                 : "=r"(r[0]), "=r"(r[1]), "=r"(r[2]), "=r"(r[3]) : "r"(a));
}
__device__ __forceinline__ void mma16816(float* c, const uint32_t* a, const uint32_t* b) {
    asm volatile(
        "mma.sync.aligned.m16n8k16.row.col.f32.bf16.bf16.f32 "
        "{%0,%1,%2,%3}, {%4,%5,%6,%7}, {%8,%9}, {%0,%1,%2,%3};"
        : "+f"(c[0]), "+f"(c[1]), "+f"(c[2]), "+f"(c[3])
        : "r"(a[0]), "r"(a[1]), "r"(a[2]), "r"(a[3]), "r"(b[0]), "r"(b[1]));
}
#define CPA(d, s) asm volatile("cp.async.cg.shared.global [%0], [%1], 16;" :: "r"(d), "l"(s))
#define CPC()     asm volatile("cp.async.commit_group;" ::: "memory")

__device__ __forceinline__ void split1(float x, __nv_bfloat16& h, __nv_bfloat16& l) {
    h = __float2bfloat16(x);
    l = __float2bfloat16(x - __bfloat162float(h));
}

// SMEM stage layout (bf16, row stride 72 elems = 144B, 128 rows each)
#define TILE_B   18432u          // 128*144
#define AH_O 0u
#define AL_O 18432u
#define BH_O 36864u
#define BL_O 55296u
#define STAGE_B  73728u
#define DYN_SMEM (2 * 73728)

// =====================================================================
// split_x: X fp32 -> Xh, Xl bf16
// =====================================================================
__global__ __launch_bounds__(256) void split_x_kernel(const float* __restrict__ X)
{
    const size_t i = ((size_t)blockIdx.x * 256 + threadIdx.x) * 8;
    float4 v0 = *reinterpret_cast<const float4*>(X + i);
    float4 v1 = *reinterpret_cast<const float4*>(X + i + 4);
    float v[8] = {v0.x, v0.y, v0.z, v0.w, v1.x, v1.y, v1.z, v1.w};
    ushort hh[8], ll[8];
    #pragma unroll
    for (int j = 0; j < 8; ++j) {
        __nv_bfloat16 h, l; split1(v[j], h, l);
        hh[j] = __bfloat16_as_ushort(h); ll[j] = __bfloat16_as_ushort(l);
    }
    uint4 hv, lv;
    hv.x = hh[0] | ((uint32_t)hh[1] << 16); hv.y = hh[2] | ((uint32_t)hh[3] << 16);
    hv.z = hh[4] | ((uint32_t)hh[5] << 16); hv.w = hh[6] | ((uint32_t)hh[7] << 16);
    lv.x = ll[0] | ((uint32_t)ll[1] << 16); lv.y = ll[2] | ((uint32_t)ll[3] << 16);
    lv.z = ll[4] | ((uint32_t)ll[5] << 16); lv.w = ll[6] | ((uint32_t)ll[7] << 16);
    *reinterpret_cast<uint4*>(&g_Xh[i]) = hv;
    *reinterpret_cast<uint4*>(&g_Xl[i]) = lv;
}

// =====================================================================
// prep_w: transpose + split weights into g_Bth/g_Btl [n][k]; pack bias
// =====================================================================
__global__ void prep_w_kernel(
    const float* __restrict__ Wq, const float* __restrict__ Wk, const float* __restrict__ Wv,
    const float* __restrict__ bq, const float* __restrict__ bk, const float* __restrict__ bv)
{
    __shared__ float tile[32][33];
    const int k0 = blockIdx.x * 32, n0g = blockIdx.y * 32;
    const float* W; const float* bias;
    if (n0g < 512)       { W = Wq; bias = bq; }
    else if (n0g < 1024) { W = Wk; bias = bk; }
    else                 { W = Wv; bias = bv; }
    const int nn0 = n0g & 511;
    const int tx = threadIdx.x, ty = threadIdx.y;
    #pragma unroll
    for (int i = 0; i < 4; ++i)
        tile[ty + i * 8][tx] = W[(size_t)(k0 + ty + i * 8) * 512 + nn0 + tx];
    __syncthreads();
    #pragma unroll
    for (int i = 0; i < 4; ++i) {
        float x = tile[tx][ty + i * 8];
        __nv_bfloat16 h, l; split1(x, h, l);
        size_t o = (size_t)(n0g + ty + i * 8) * 512 + k0 + tx;
        g_Bth[o] = h; g_Btl[o] = l;
    }
    if (blockIdx.x == 0 && ty == 0) g_biasC[n0g + tx] = bias[nn0 + tx];
}

// =====================================================================
// HMMA GEMM: C[128x128 tile] = A @ B^T with 3-term bf16 split.
// A[m][k] bf16 hi/lo, B[n][k] bf16 hi/lo (k contiguous both).
// 256 thr = 8 warps (2 M x 4 N), warp tile 64x32, mma m16n8k16.
// =====================================================================
__device__ __forceinline__ void stage_load(
    uint32_t sdst,
    const __nv_bfloat16* __restrict__ Ah, const __nv_bfloat16* __restrict__ Al,
    const __nv_bfloat16* __restrict__ Bh, const __nv_bfloat16* __restrict__ Bl,
    int tid, int m0, int n0, int k0)
{
    #pragma unroll
    for (int j = 0; j < 4; ++j) {
        const int idx = tid + j * 256;
        const int row = idx >> 3, seg = idx & 7;
        const uint32_t d = sdst + (uint32_t)row * 144u + (uint32_t)seg * 16u;
        const size_t ga = (size_t)(m0 + row) * 512 + k0 + seg * 8;
        const size_t gb = (size_t)(n0 + row) * 512 + k0 + seg * 8;
        CPA(d + AH_O, Ah + ga);
        CPA(d + AL_O, Al + ga);
        CPA(d + BH_O, Bh + gb);
        CPA(d + BL_O, Bl + gb);
    }
}

template<bool QKV>
__global__ __launch_bounds__(256) void hmma_gemm_kernel(
    const float* __restrict__ biasIn, float* __restrict__ Cout)
{
    extern __shared__ char smem[];
    const uint32_t sb = smem_u32(smem);
    const int tid = threadIdx.x, lane = tid & 31, warp = tid >> 5;
    const int wm = warp >> 2, wn = warp & 3;
    const int m0 = blockIdx.y * 128, n0 = blockIdx.x * 128;

    const __nv_bfloat16 *Agh, *Agl, *Bgh, *Bgl;
    if (QKV) { Agh = g_Xh; Agl = g_Xl; Bgh = g_Bth; Bgl = g_Btl; }
    else {
        Agh = g_qsh; Agl = g_qsl;
        const size_t boff = (size_t)(m0 >> 13) * 512 * 512;
        Bgh = g_Mth + boff; Bgl = g_Mtl + boff;
    }

    float acc[4][4][4];
    #pragma unroll
    for (int i = 0; i < 4; ++i)
        #pragma unroll
        for (int j = 0; j < 4; ++j)
            #pragma unroll
            for (int u = 0; u < 4; ++u) acc[i][j][u] = 0.f;

    // ldmatrix lane addressing
    const int a_r  = lane & 15;
    const int a_c  = (lane >> 4) << 3;       // 0 or 8
    const int bg   = lane >> 3;
    const int b_nr = ((bg & 2) << 2) + (lane & 7);
    const int b_ka = (bg & 1) << 3;

    stage_load(sb, Agh, Agl, Bgh, Bgl, tid, m0, n0, 0);
    CPC();

    #pragma unroll 1
    for (int c = 0; c < 8; ++c) {
        if (c < 7) {
            stage_load(sb + (uint32_t)((c + 1) & 1) * STAGE_B, Agh, Agl, Bgh, Bgl,
                       tid, m0, n0, (c + 1) * 64);
            CPC();
            asm volatile("cp.async.wait_group 1;" ::: "memory");
        } else {
            asm volatile("cp.async.wait_group 0;" ::: "memory");
        }
        __syncthreads();

        const uint32_t s0 = sb + (uint32_t)(c & 1) * STAGE_B;
        #pragma unroll
        for (int ks = 0; ks < 4; ++ks) {
            uint32_t ah[4][4], al[4][4], bh[4][2], bl[4][2];
            #pragma unroll
            for (int mt = 0; mt < 4; ++mt) {
                const uint32_t aoff = (uint32_t)((wm * 64 + mt * 16 + a_r) * 144
                                                 + (ks * 16 + a_c) * 2);
                ldsm4(ah[mt], s0 + AH_O + aoff);
                ldsm4(al[mt], s0 + AL_O + aoff);
            }
            #pragma unroll
            for (int p = 0; p < 2; ++p) {
                const uint32_t boff = (uint32_t)((wn * 32 + p * 16 + b_nr) * 144
                                                 + (ks * 16 + b_ka) * 2);
                uint32_t r[4];
                ldsm4(r, s0 + BH_O + boff);
                bh[2 * p][0] = r[0]; bh[2 * p][1] = r[1];
                bh[2 * p + 1][0] = r[2]; bh[2 * p + 1][1] = r[3];
                ldsm4(r, s0 + BL_O + boff);
                bl[2 * p][0] = r[0]; bl[2 * p][1] = r[1];
                bl[2 * p + 1][0] = r[2]; bl[2 * p + 1][1] = r[3];
            }
            #pragma unroll
            for (int mt = 0; mt < 4; ++mt)
                #pragma unroll
                for (int nt = 0; nt < 4; ++nt) {
                    mma16816(acc[mt][nt], ah[mt], bh[nt]);
                    mma16816(acc[mt][nt], ah[mt], bl[nt]);
                    mma16816(acc[mt][nt], al[mt], bh[nt]);
                }
        }
        __syncthreads();
    }

    // ---- epilogue: direct f32x2 stores + bias ----
    const int r0 = m0 + wm * 64 + (lane >> 2);
    const int c0 = n0 + wn * 32 + (lane & 3) * 2;
    #pragma unroll
    for (int mt = 0; mt < 4; ++mt) {
        #pragma unroll
        for (int nt = 0; nt < 4; ++nt) {
            const int rr = r0 + mt * 16;
            const int cc = c0 + nt * 8;
            float bx, by;
            float* dst;
            if (QKV) {
                const int mat = cc >> 9, c2 = cc & 511;
                bx = g_biasC[cc]; by = g_biasC[cc + 1];
                dst = g_qkv + (size_t)mat * BN_ROWS * 512 + (size_t)rr * 512 + c2;
            } else {
                bx = biasIn[cc]; by = biasIn[cc + 1];
                dst = Cout + (size_t)rr * 512 + cc;
            }
            float2 v0 = make_float2(acc[mt][nt][0] + bx, acc[mt][nt][1] + by);
            float2 v1 = make_float2(acc[mt][nt][2] + bx, acc[mt][nt][3] + by);
            *reinterpret_cast<float2*>(dst) = v0;
            *reinterpret_cast<float2*>(dst + 8 * 512) = v1;
        }
    }
}

// =====================================================================
// qsplit: per (row, head) qinv = gamma[h]/||q_head||; write (q*qinv) split bf16
// One warp per row; lane handles 16 contiguous elems (head = lane/4).
// =====================================================================
__global__ __launch_bounds__(256) void qsplit_kernel(const float* __restrict__ gamma)
{
    const int warp = threadIdx.x >> 5;
    const int lane = threadIdx.x & 31;
    const size_t row = (size_t)blockIdx.x * 8 + warp;
    const float* qr = g_qkv + row * 512 + lane * 16;

    float v[16];
    #pragma unroll
    for (int j = 0; j < 4; ++j) {
        float4 t = *reinterpret_cast<const float4*>(qr + j * 4);
        v[j * 4 + 0] = t.x; v[j * 4 + 1] = t.y; v[j * 4 + 2] = t.z; v[j * 4 + 3] = t.w;
    }
    float s = 0.f;
    #pragma unroll
    for (int j = 0; j < 16; ++j) s = fmaf(v[j], v[j], s);
    s += __shfl_xor_sync(0xffffffffu, s, 1);
    s += __shfl_xor_sync(0xffffffffu, s, 2);
    const float sc = gamma[lane >> 2] / sqrtf(s);

    ushort hh[16], ll[16];
    #pragma unroll
    for (int j = 0; j < 16; ++j) {
        __nv_bfloat16 h, l; split1(v[j] * sc, h, l);
        hh[j] = __bfloat16_as_ushort(h); ll[j] = __bfloat16_as_ushort(l);
    }
    uint4 o;
    const size_t base = row * 512 + lane * 16;
    o.x = hh[0] | ((uint32_t)hh[1] << 16); o.y = hh[2] | ((uint32_t)hh[3] << 16);
    o.z = hh[4] | ((uint32_t)hh[5] << 16); o.w = hh[6] | ((uint32_t)hh[7] << 16);
    *reinterpret_cast<uint4*>(&g_qsh[base]) = o;
    o.x = hh[8] | ((uint32_t)hh[9] << 16); o.y = hh[10] | ((uint32_t)hh[11] << 16);
    o.z = hh[12] | ((uint32_t)hh[13] << 16); o.w = hh[14] | ((uint32_t)hh[15] << 16);
    *reinterpret_cast<uint4*>(&g_qsh[base + 8]) = o;
    o.x = ll[0] | ((uint32_t)ll[1] << 16); o.y = ll[2] | ((uint32_t)ll[3] << 16);
    o.z = ll[4] | ((uint32_t)ll[5] << 16); o.w = ll[6] | ((uint32_t)ll[7] << 16);
    *reinterpret_cast<uint4*>(&g_qsl[base]) = o;
    o.x = ll[8] | ((uint32_t)ll[9] << 16); o.y = ll[10] | ((uint32_t)ll[11] << 16);
    o.z = ll[12] | ((uint32_t)ll[13] << 16); o.w = ll[14] | ((uint32_t)ll[15] << 16);
    *reinterpret_cast<uint4*>(&g_qsl[base + 8]) = o;
}

// =====================================================================
// kv partial outer products (fp32 SIMT, memory-bound)
// =====================================================================
__global__ __launch_bounds__(256) void kv_partial_kernel()
{
    const int chunk = blockIdx.x;
    const int bh    = blockIdx.y;
    const int b     = bh >> 3;
    const int h     = bh & 7;

    const float* kk = g_qkv + (size_t)1 * BN_ROWS * D_;
    const float* vv = g_qkv + (size_t)2 * BN_ROWS * D_;

    __shared__ float ks[16][68];
    __shared__ float vs[16][68];

    const int tid = threadIdx.x;
    const int lr  = tid >> 4;
    const int lc4 = (tid & 15) << 2;
    const int tx  = tid & 15;
    const int ty  = tid >> 4;

    float acc[4][4];
    #pragma unroll
    for (int i = 0; i < 4; i++)
        #pragma unroll
        for (int j = 0; j < 4; j++) acc[i][j] = 0.f;

    const size_t base = (size_t)b * N_ * D_ + h * 64;
    const int nbeg = chunk * 1024;
    for (int n0 = nbeg; n0 < nbeg + 1024; n0 += 16) {
        const size_t off = base + (size_t)(n0 + lr) * D_ + lc4;
        *reinterpret_cast<float4*>(&ks[lr][lc4]) = *reinterpret_cast<const float4*>(&kk[off]);
        *reinterpret_cast<float4*>(&vs[lr][lc4]) = *reinterpret_cast<const float4*>(&vv[off]);
        __syncthreads();
        #pragma unroll
        for (int nn = 0; nn < 16; nn++) {
            float a[4], w[4];
            #pragma unroll
            for (int i = 0; i < 4; i++) a[i] = ks[nn][ty * 4 + i];
            #pragma unroll
            for (int j = 0; j < 4; j++) w[j] = vs[nn][tx * 4 + j];
            #pragma unroll
            for (int i = 0; i < 4; i++)
                #pragma unroll
                for (int j = 0; j < 4; j++) acc[i][j] = fmaf(a[i], w[j], acc[i][j]);
        }
        __syncthreads();
    }

    float* P = g_kvp + ((size_t)bh * 8 + chunk) * 4096;
    #pragma unroll
    for (int i = 0; i < 4; i++) {
        float4 o = make_float4(acc[i][0], acc[i][1], acc[i][2], acc[i][3]);
        *reinterpret_cast<float4*>(&P[(ty * 4 + i) * 64 + tx * 4]) = o;
    }
}

// =====================================================================
// kv reduce + normalize + fold Wo -> Mt[b][d][k] (transposed, bf16 hi/lo)
// =====================================================================
__global__ __launch_bounds__(256) void kv_reduce_M_kernel(
    const float* __restrict__ Wo, const float* __restrict__ gamma)
{
    const int bh = blockIdx.x;
    const int b  = bh >> 3;
    const int h  = bh & 7;

    __shared__ float kvs[64][65];
    __shared__ float wos[64][65];
    __shared__ float mts[64][65];
    __shared__ float rs[64];

    const int tid = threadIdx.x;

    for (int idx = tid; idx < 4096; idx += 256) {
        float s = 0.f;
        #pragma unroll
        for (int p = 0; p < 8; p++) s += g_kvp[((size_t)bh * 8 + p) * 4096 + idx];
        kvs[idx >> 6][idx & 63] = s;
    }
    __syncthreads();

    if (tid < 64) {
        float s = 0.f;
        #pragma unroll
        for (int c = 0; c < 64; c++) { float x = kvs[tid][c]; s = fmaf(x, x, s); }
        rs[tid] = gamma[h] / sqrtf(s);
    }
    __syncthreads();

    const int tx = tid & 15;
    const int ty = tid >> 4;
    const int dcol = tid >> 2;
    const int seg  = (tid & 3) * 16;

    for (int dt = 0; dt < 8; dt++) {
        const int d0 = dt * 64;
        for (int idx = tid; idx < 4096; idx += 256) {
            const int dv = idx >> 6, dd = idx & 63;
            wos[dv][dd] = Wo[(size_t)(h * 64 + dv) * D_ + d0 + dd];
        }
        __syncthreads();

        float acc[4][4];
        #pragma unroll
        for (int i = 0; i < 4; i++)
            #pragma unroll
            for (int j = 0; j < 4; j++) acc[i][j] = 0.f;

        #pragma unroll 8
        for (int dv = 0; dv < 64; dv++) {
            float a[4], w[4];
            #pragma unroll
            for (int i = 0; i < 4; i++) a[i] = kvs[ty * 4 + i][dv];
            #pragma unroll
            for (int j = 0; j < 4; j++) w[j] = wos[dv][tx * 4 + j];
            #pragma unroll
            for (int i = 0; i < 4; i++)
                #pragma unroll
                for (int j = 0; j < 4; j++) acc[i][j] = fmaf(a[i], w[j], acc[i][j]);
        }

        #pragma unroll
        for (int i = 0; i < 4; i++) {
            const float sc = rs[ty * 4 + i];
            #pragma unroll
            for (int j = 0; j < 4; j++) mts[ty * 4 + i][tx * 4 + j] = acc[i][j] * sc;
        }
        __syncthreads();

        uint32_t hw[8], lw[8];
        #pragma unroll
        for (int u = 0; u < 8; ++u) {
            float x0 = mts[seg + 2 * u][dcol];
            float x1 = mts[seg + 2 * u + 1][dcol];
            __nv_bfloat16 h0, l0, h1, l1;
            split1(x0, h0, l0); split1(x1, h1, l1);
            hw[u] = (uint32_t)__bfloat16_as_ushort(h0) | ((uint32_t)__bfloat16_as_ushort(h1) << 16);
            lw[u] = (uint32_t)__bfloat16_as_ushort(l0) | ((uint32_t)__bfloat16_as_ushort(l1) << 16);
        }
        const size_t o = ((size_t)b * 512 + d0 + dcol) * 512 + h * 64 + seg;
        uint4* ph = reinterpret_cast<uint4*>(&g_Mth[o]);
        uint4* pl = reinterpret_cast<uint4*>(&g_Mtl[o]);
        ph[0] = make_uint4(hw[0], hw[1], hw[2], hw[3]);
        ph[1] = make_uint4(hw[4], hw[5], hw[6], hw[7]);
        pl[0] = make_uint4(lw[0], lw[1], lw[2], lw[3]);
        pl[1] = make_uint4(lw[4], lw[5], lw[6], lw[7]);
        __syncthreads();
    }
}

// =====================================================================
extern "C" void kernel_launch(void* const* d_in, const int* in_sizes, int n_in,
                              void* d_out, int out_size)
{
    const float* X     = (const float*)d_in[0];
    const float* Wq    = (const float*)d_in[1];
    const float* bq    = (const float*)d_in[2];
    const float* Wk    = (const float*)d_in[3];
    const float* bk    = (const float*)d_in[4];
    const float* Wv    = (const float*)d_in[5];
    const float* bv    = (const float*)d_in[6];
    const float* Wo    = (const float*)d_in[7];
    const float* bo    = (const float*)d_in[8];
    const float* gamma = (const float*)d_in[9];
    float* out = (float*)d_out;

    static bool attr_set = false;
    if (!attr_set) {
        cudaFuncSetAttribute(hmma_gemm_kernel<true>,  cudaFuncAttributeMaxDynamicSharedMemorySize, DYN_SMEM);
        cudaFuncSetAttribute(hmma_gemm_kernel<false>, cudaFuncAttributeMaxDynamicSharedMemorySize, DYN_SMEM);
        attr_set = true;
    }

    // 1) split X into bf16 hi/lo
    split_x_kernel<<<16384, 256>>>(X);
    // 2) transpose+split weights, pack biases
    prep_w_kernel<<<dim3(16, 48), dim3(32, 8)>>>(Wq, Wk, Wv, bq, bk, bv);
    // 3) fused QKV projection on tensor cores (HMMA)
    hmma_gemm_kernel<true><<<dim3(12, 512), 256, DYN_SMEM>>>(nullptr, nullptr);
    // 4) q norms + scale + split
    qsplit_kernel<<<BN_ROWS / 8, 256>>>(gamma);
    // 5) kv partial outer products
    kv_partial_kernel<<<dim3(8, 64), 256>>>();
    // 6) reduce kv, normalize, fold Wo -> Mt (bf16 hi/lo)
    kv_reduce_M_kernel<<<64, 256>>>(Wo, gamma);
    // 7) out = q_n @ Mt^T + bo on tensor cores
    hmma_gemm_kernel<false><<<dim3(4, 512), 256, DYN_SMEM>>>(bo, out);
}

// round 4
// speedup vs baseline: 2.5011x; 1.0693x over previous
#include <cuda_runtime.h>
#include <cuda_bf16.h>
#include <math.h>
#include <stdint.h>

#define B_   8
#define N_   8192
#define D_   512
#define H_   8
#define BN_ROWS 65536

// ---------------- scratch (static device arrays) ----------------
__device__ float g_qkv[(size_t)3 * BN_ROWS * D_];            // q | k | v fp32
__device__ __nv_bfloat16 g_Xh[(size_t)BN_ROWS * D_];
__device__ __nv_bfloat16 g_Xl[(size_t)BN_ROWS * D_];
__device__ __nv_bfloat16 g_qsh[(size_t)BN_ROWS * D_];        // q * qinv, split
__device__ __nv_bfloat16 g_qsl[(size_t)BN_ROWS * D_];
__device__ __nv_bfloat16 g_Bth[1536 * 512];                  // [n][k] Wq|Wk|Wv^T hi
__device__ __nv_bfloat16 g_Btl[1536 * 512];
__device__ float g_biasC[1536];
__device__ float g_kvp[(size_t)64 * 8 * 4096];
__device__ __nv_bfloat16 g_Mth[(size_t)B_ * 512 * 512];      // Mt[b][d][k] hi
__device__ __nv_bfloat16 g_Mtl[(size_t)B_ * 512 * 512];

// ---------------- helpers ----------------
__device__ __forceinline__ uint32_t smem_u32(const void* p) {
    uint32_t a;
    asm("{ .reg .u64 t; cvta.to.shared.u64 t, %1; cvt.u32.u64 %0, t; }" : "=r"(a) : "l"(p));
    return a;
}
__device__ __forceinline__ void ldsm4(uint32_t* r, uint32_t a) {
    asm volatile("ldmatrix.sync.aligned.m8n8.x4.shared.b16 {%0,%1,%2,%3}, [%4];"
                 : "=r"(r[0]), "=r"(r[1]), "=r"(r[2]), "=r"(r[3]) : "r"(a));
}
__device__ __forceinline__ void mma16816(float* c, const uint32_t* a, const uint32_t* b) {
    asm volatile(
        "mma.sync.aligned.m16n8k16.row.col.f32.bf16.bf16.f32 "
        "{%0,%1,%2,%3}, {%4,%5,%6,%7}, {%8,%9}, {%0,%1,%2,%3};"
        : "+f"(c[0]), "+f"(c[1]), "+f"(c[2]), "+f"(c[3])
        : "r"(a[0]), "r"(a[1]), "r"(a[2]), "r"(a[3]), "r"(b[0]), "r"(b[1]));
}
#define CPA(d, s) asm volatile("cp.async.cg.shared.global [%0], [%1], 16;" :: "r"(d), "l"(s))
#define CPC()     asm volatile("cp.async.commit_group;" ::: "memory")

__device__ __forceinline__ void split1(float x, __nv_bfloat16& h, __nv_bfloat16& l) {
    h = __float2bfloat16(x);
    l = __float2bfloat16(x - __bfloat162float(h));
}

// SMEM stage layout (bf16, row stride 72 elems = 144B)
// A: 128 rows (h, l), B: 256 rows (h, l), k-chunk 64
#define AH_O 0u
#define AL_O 18432u
#define BH_O 36864u
#define BL_O 73728u
#define STAGE_B  110592u
#define DYN_SMEM (2 * 110592)

// =====================================================================
// split_x: X fp32 -> Xh, Xl bf16
// =====================================================================
__global__ __launch_bounds__(256) void split_x_kernel(const float* __restrict__ X)
{
    const size_t i = ((size_t)blockIdx.x * 256 + threadIdx.x) * 8;
    float4 v0 = *reinterpret_cast<const float4*>(X + i);
    float4 v1 = *reinterpret_cast<const float4*>(X + i + 4);
    float v[8] = {v0.x, v0.y, v0.z, v0.w, v1.x, v1.y, v1.z, v1.w};
    ushort hh[8], ll[8];
    #pragma unroll
    for (int j = 0; j < 8; ++j) {
        __nv_bfloat16 h, l; split1(v[j], h, l);
        hh[j] = __bfloat16_as_ushort(h); ll[j] = __bfloat16_as_ushort(l);
    }
    uint4 hv, lv;
    hv.x = hh[0] | ((uint32_t)hh[1] << 16); hv.y = hh[2] | ((uint32_t)hh[3] << 16);
    hv.z = hh[4] | ((uint32_t)hh[5] << 16); hv.w = hh[6] | ((uint32_t)hh[7] << 16);
    lv.x = ll[0] | ((uint32_t)ll[1] << 16); lv.y = ll[2] | ((uint32_t)ll[3] << 16);
    lv.z = ll[4] | ((uint32_t)ll[5] << 16); lv.w = ll[6] | ((uint32_t)ll[7] << 16);
    *reinterpret_cast<uint4*>(&g_Xh[i]) = hv;
    *reinterpret_cast<uint4*>(&g_Xl[i]) = lv;
}

// =====================================================================
// prep_w: transpose + split weights into g_Bth/g_Btl [n][k]; pack bias
// =====================================================================
__global__ void prep_w_kernel(
    const float* __restrict__ Wq, const float* __restrict__ Wk, const float* __restrict__ Wv,
    const float* __restrict__ bq, const float* __restrict__ bk, const float* __restrict__ bv)
{
    __shared__ float tile[32][33];
    const int k0 = blockIdx.x * 32, n0g = blockIdx.y * 32;
    const float* W; const float* bias;
    if (n0g < 512)       { W = Wq; bias = bq; }
    else if (n0g < 1024) { W = Wk; bias = bk; }
    else                 { W = Wv; bias = bv; }
    const int nn0 = n0g & 511;
    const int tx = threadIdx.x, ty = threadIdx.y;
    #pragma unroll
    for (int i = 0; i < 4; ++i)
        tile[ty + i * 8][tx] = W[(size_t)(k0 + ty + i * 8) * 512 + nn0 + tx];
    __syncthreads();
    #pragma unroll
    for (int i = 0; i < 4; ++i) {
        float x = tile[tx][ty + i * 8];
        __nv_bfloat16 h, l; split1(x, h, l);
        size_t o = (size_t)(n0g + ty + i * 8) * 512 + k0 + tx;
        g_Bth[o] = h; g_Btl[o] = l;
    }
    if (blockIdx.x == 0 && ty == 0) g_biasC[n0g + tx] = bias[nn0 + tx];
}

// =====================================================================
// HMMA GEMM: CTA tile 128x256, warp tile 64x64 (8 warps = 2M x 4N).
// C = A @ B^T, 3-term bf16 split. A[m][k], B[n][k], k contiguous.
// =====================================================================
__device__ __forceinline__ void stage_load(
    uint32_t sdst,
    const __nv_bfloat16* __restrict__ Ah, const __nv_bfloat16* __restrict__ Al,
    const __nv_bfloat16* __restrict__ Bh, const __nv_bfloat16* __restrict__ Bl,
    int tid, int m0, int n0, int k0)
{
    #pragma unroll
    for (int j = 0; j < 4; ++j) {                 // A: 128 rows x 8 segs
        const int idx = tid + j * 256;
        const int row = idx >> 3, seg = idx & 7;
        const uint32_t d = sdst + (uint32_t)row * 144u + (uint32_t)seg * 16u;
        const size_t g = (size_t)(m0 + row) * 512 + k0 + seg * 8;
        CPA(d + AH_O, Ah + g);
        CPA(d + AL_O, Al + g);
    }
    #pragma unroll
    for (int j = 0; j < 8; ++j) {                 // B: 256 rows x 8 segs
        const int idx = tid + j * 256;
        const int row = idx >> 3, seg = idx & 7;
        const uint32_t d = sdst + (uint32_t)row * 144u + (uint32_t)seg * 16u;
        const size_t g = (size_t)(n0 + row) * 512 + k0 + seg * 8;
        CPA(d + BH_O, Bh + g);
        CPA(d + BL_O, Bl + g);
    }
}

template<bool QKV>
__global__ __launch_bounds__(256, 1) void hmma_gemm_kernel(
    const float* __restrict__ biasIn, float* __restrict__ Cout)
{
    extern __shared__ char smem[];
    const uint32_t sb = smem_u32(smem);
    const int tid = threadIdx.x, lane = tid & 31, warp = tid >> 5;
    const int wm = warp >> 2, wn = warp & 3;      // 2 x 4 warp grid
    const int m0 = blockIdx.y * 128, n0 = blockIdx.x * 256;

    const __nv_bfloat16 *Agh, *Agl, *Bgh, *Bgl;
    if (QKV) { Agh = g_Xh; Agl = g_Xl; Bgh = g_Bth; Bgl = g_Btl; }
    else {
        Agh = g_qsh; Agl = g_qsl;
        const size_t boff = (size_t)(m0 >> 13) * 512 * 512;
        Bgh = g_Mth + boff; Bgl = g_Mtl + boff;
    }

    float acc[4][8][4];
    #pragma unroll
    for (int i = 0; i < 4; ++i)
        #pragma unroll
        for (int j = 0; j < 8; ++j)
            #pragma unroll
            for (int u = 0; u < 4; ++u) acc[i][j][u] = 0.f;

    // ldmatrix lane addressing
    const int a_r  = lane & 15;
    const int a_c  = (lane >> 4) << 3;            // 0 or 8
    const int bg   = lane >> 3;
    const int b_nr = ((bg & 2) << 2) + (lane & 7);
    const int b_ka = (bg & 1) << 3;

    stage_load(sb, Agh, Agl, Bgh, Bgl, tid, m0, n0, 0);
    CPC();

    #pragma unroll 1
    for (int c = 0; c < 8; ++c) {
        if (c < 7) {
            stage_load(sb + (uint32_t)((c + 1) & 1) * STAGE_B, Agh, Agl, Bgh, Bgl,
                       tid, m0, n0, (c + 1) * 64);
            CPC();
            asm volatile("cp.async.wait_group 1;" ::: "memory");
        } else {
            asm volatile("cp.async.wait_group 0;" ::: "memory");
        }
        __syncthreads();

        const uint32_t s0 = sb + (uint32_t)(c & 1) * STAGE_B;
        #pragma unroll
        for (int ks = 0; ks < 4; ++ks) {
            uint32_t ah[4][4], al[4][4];
            #pragma unroll
            for (int mt = 0; mt < 4; ++mt) {
                const uint32_t aoff = (uint32_t)((wm * 64 + mt * 16 + a_r) * 144
                                                 + (ks * 16 + a_c) * 2);
                ldsm4(ah[mt], s0 + AH_O + aoff);
                ldsm4(al[mt], s0 + AL_O + aoff);
            }
            #pragma unroll
            for (int g = 0; g < 4; ++g) {        // 4 groups of 16 N-cols
                const uint32_t boff = (uint32_t)((wn * 64 + g * 16 + b_nr) * 144
                                                 + (ks * 16 + b_ka) * 2);
                uint32_t bh4[4], bl4[4];
                ldsm4(bh4, s0 + BH_O + boff);
                ldsm4(bl4, s0 + BL_O + boff);
                #pragma unroll
                for (int mt = 0; mt < 4; ++mt) {
                    mma16816(acc[mt][2 * g],     ah[mt], bh4);
                    mma16816(acc[mt][2 * g],     ah[mt], bl4);
                    mma16816(acc[mt][2 * g],     al[mt], bh4);
                    mma16816(acc[mt][2 * g + 1], ah[mt], bh4 + 2);
                    mma16816(acc[mt][2 * g + 1], ah[mt], bl4 + 2);
                    mma16816(acc[mt][2 * g + 1], al[mt], bh4 + 2);
                }
            }
        }
        __syncthreads();
    }

    // ---- epilogue: direct f32x2 stores + bias ----
    const int r0 = m0 + wm * 64 + (lane >> 2);
    const int c0 = n0 + wn * 64 + (lane & 3) * 2;
    #pragma unroll
    for (int mt = 0; mt < 4; ++mt) {
        #pragma unroll
        for (int nt = 0; nt < 8; ++nt) {
            const int rr = r0 + mt * 16;
            const int cc = c0 + nt * 8;
            float bx, by;
            float* dst;
            if (QKV) {
                const int mat = cc >> 9, c2 = cc & 511;
                bx = g_biasC[cc]; by = g_biasC[cc + 1];
                dst = g_qkv + (size_t)mat * BN_ROWS * 512 + (size_t)rr * 512 + c2;
            } else {
                bx = biasIn[cc]; by = biasIn[cc + 1];
                dst = Cout + (size_t)rr * 512 + cc;
            }
            float2 v0 = make_float2(acc[mt][nt][0] + bx, acc[mt][nt][1] + by);
            float2 v1 = make_float2(acc[mt][nt][2] + bx, acc[mt][nt][3] + by);
            *reinterpret_cast<float2*>(dst) = v0;
            *reinterpret_cast<float2*>(dst + 8 * 512) = v1;
        }
    }
}

// =====================================================================
// qsplit: per (row, head) qinv = gamma[h]/||q_head||; write (q*qinv) split bf16
// =====================================================================
__global__ __launch_bounds__(256) void qsplit_kernel(const float* __restrict__ gamma)
{
    const int warp = threadIdx.x >> 5;
    const int lane = threadIdx.x & 31;
    const size_t row = (size_t)blockIdx.x * 8 + warp;
    const float* qr = g_qkv + row * 512 + lane * 16;

    float v[16];
    #pragma unroll
    for (int j = 0; j < 4; ++j) {
        float4 t = *reinterpret_cast<const float4*>(qr + j * 4);
        v[j * 4 + 0] = t.x; v[j * 4 + 1] = t.y; v[j * 4 + 2] = t.z; v[j * 4 + 3] = t.w;
    }
    float s = 0.f;
    #pragma unroll
    for (int j = 0; j < 16; ++j) s = fmaf(v[j], v[j], s);
    s += __shfl_xor_sync(0xffffffffu, s, 1);
    s += __shfl_xor_sync(0xffffffffu, s, 2);
    const float sc = gamma[lane >> 2] / sqrtf(s);

    ushort hh[16], ll[16];
    #pragma unroll
    for (int j = 0; j < 16; ++j) {
        __nv_bfloat16 h, l; split1(v[j] * sc, h, l);
        hh[j] = __bfloat16_as_ushort(h); ll[j] = __bfloat16_as_ushort(l);
    }
    uint4 o;
    const size_t base = row * 512 + lane * 16;
    o.x = hh[0] | ((uint32_t)hh[1] << 16); o.y = hh[2] | ((uint32_t)hh[3] << 16);
    o.z = hh[4] | ((uint32_t)hh[5] << 16); o.w = hh[6] | ((uint32_t)hh[7] << 16);
    *reinterpret_cast<uint4*>(&g_qsh[base]) = o;
    o.x = hh[8] | ((uint32_t)hh[9] << 16); o.y = hh[10] | ((uint32_t)hh[11] << 16);
    o.z = hh[12] | ((uint32_t)hh[13] << 16); o.w = hh[14] | ((uint32_t)hh[15] << 16);
    *reinterpret_cast<uint4*>(&g_qsh[base + 8]) = o;
    o.x = ll[0] | ((uint32_t)ll[1] << 16); o.y = ll[2] | ((uint32_t)ll[3] << 16);
    o.z = ll[4] | ((uint32_t)ll[5] << 16); o.w = ll[6] | ((uint32_t)ll[7] << 16);
    *reinterpret_cast<uint4*>(&g_qsl[base]) = o;
    o.x = ll[8] | ((uint32_t)ll[9] << 16); o.y = ll[10] | ((uint32_t)ll[11] << 16);
    o.z = ll[12] | ((uint32_t)ll[13] << 16); o.w = ll[14] | ((uint32_t)ll[15] << 16);
    *reinterpret_cast<uint4*>(&g_qsl[base + 8]) = o;
}

// =====================================================================
// kv partial outer products (fp32 SIMT, memory-bound)
// =====================================================================
__global__ __launch_bounds__(256) void kv_partial_kernel()
{
    const int chunk = blockIdx.x;
    const int bh    = blockIdx.y;
    const int b     = bh >> 3;
    const int h     = bh & 7;

    const float* kk = g_qkv + (size_t)1 * BN_ROWS * D_;
    const float* vv = g_qkv + (size_t)2 * BN_ROWS * D_;

    __shared__ float ks[16][68];
    __shared__ float vs[16][68];

    const int tid = threadIdx.x;
    const int lr  = tid >> 4;
    const int lc4 = (tid & 15) << 2;
    const int tx  = tid & 15;
    const int ty  = tid >> 4;

    float acc[4][4];
    #pragma unroll
    for (int i = 0; i < 4; i++)
        #pragma unroll
        for (int j = 0; j < 4; j++) acc[i][j] = 0.f;

    const size_t base = (size_t)b * N_ * D_ + h * 64;
    const int nbeg = chunk * 1024;
    for (int n0 = nbeg; n0 < nbeg + 1024; n0 += 16) {
        const size_t off = base + (size_t)(n0 + lr) * D_ + lc4;
        *reinterpret_cast<float4*>(&ks[lr][lc4]) = *reinterpret_cast<const float4*>(&kk[off]);
        *reinterpret_cast<float4*>(&vs[lr][lc4]) = *reinterpret_cast<const float4*>(&vv[off]);
        __syncthreads();
        #pragma unroll
        for (int nn = 0; nn < 16; nn++) {
            float a[4], w[4];
            #pragma unroll
            for (int i = 0; i < 4; i++) a[i] = ks[nn][ty * 4 + i];
            #pragma unroll
            for (int j = 0; j < 4; j++) w[j] = vs[nn][tx * 4 + j];
            #pragma unroll
            for (int i = 0; i < 4; i++)
                #pragma unroll
                for (int j = 0; j < 4; j++) acc[i][j] = fmaf(a[i], w[j], acc[i][j]);
        }
        __syncthreads();
    }

    float* P = g_kvp + ((size_t)bh * 8 + chunk) * 4096;
    #pragma unroll
    for (int i = 0; i < 4; i++) {
        float4 o = make_float4(acc[i][0], acc[i][1], acc[i][2], acc[i][3]);
        *reinterpret_cast<float4*>(&P[(ty * 4 + i) * 64 + tx * 4]) = o;
    }
}

// =====================================================================
// kv reduce + normalize + fold Wo -> Mt[b][d][k] (transposed, bf16 hi/lo)
// =====================================================================
__global__ __launch_bounds__(256) void kv_reduce_M_kernel(
    const float* __restrict__ Wo, const float* __restrict__ gamma)
{
    const int bh = blockIdx.x;
    const int b  = bh >> 3;
    const int h  = bh & 7;

    __shared__ float kvs[64][65];
    __shared__ float wos[64][65];
    __shared__ float mts[64][65];
    __shared__ float rs[64];

    const int tid = threadIdx.x;

    for (int idx = tid; idx < 4096; idx += 256) {
        float s = 0.f;
        #pragma unroll
        for (int p = 0; p < 8; p++) s += g_kvp[((size_t)bh * 8 + p) * 4096 + idx];
        kvs[idx >> 6][idx & 63] = s;
    }
    __syncthreads();

    if (tid < 64) {
        float s = 0.f;
        #pragma unroll
        for (int c = 0; c < 64; c++) { float x = kvs[tid][c]; s = fmaf(x, x, s); }
        rs[tid] = gamma[h] / sqrtf(s);
    }
    __syncthreads();

    const int tx = tid & 15;
    const int ty = tid >> 4;
    const int dcol = tid >> 2;
    const int seg  = (tid & 3) * 16;

    for (int dt = 0; dt < 8; dt++) {
        const int d0 = dt * 64;
        for (int idx = tid; idx < 4096; idx += 256) {
            const int dv = idx >> 6, dd = idx & 63;
            wos[dv][dd] = Wo[(size_t)(h * 64 + dv) * D_ + d0 + dd];
        }
        __syncthreads();

        float acc[4][4];
        #pragma unroll
        for (int i = 0; i < 4; i++)
            #pragma unroll
            for (int j = 0; j < 4; j++) acc[i][j] = 0.f;

        #pragma unroll 8
        for (int dv = 0; dv < 64; dv++) {
            float a[4], w[4];
            #pragma unroll
            for (int i = 0; i < 4; i++) a[i] = kvs[ty * 4 + i][dv];
            #pragma unroll
            for (int j = 0; j < 4; j++) w[j] = wos[dv][tx * 4 + j];
            #pragma unroll
            for (int i = 0; i < 4; i++)
                #pragma unroll
                for (int j = 0; j < 4; j++) acc[i][j] = fmaf(a[i], w[j], acc[i][j]);
        }

        #pragma unroll
        for (int i = 0; i < 4; i++) {
            const float sc = rs[ty * 4 + i];
            #pragma unroll
            for (int j = 0; j < 4; j++) mts[ty * 4 + i][tx * 4 + j] = acc[i][j] * sc;
        }
        __syncthreads();

        uint32_t hw[8], lw[8];
        #pragma unroll
        for (int u = 0; u < 8; ++u) {
            float x0 = mts[seg + 2 * u][dcol];
            float x1 = mts[seg + 2 * u + 1][dcol];
            __nv_bfloat16 h0, l0, h1, l1;
            split1(x0, h0, l0); split1(x1, h1, l1);
            hw[u] = (uint32_t)__bfloat16_as_ushort(h0) | ((uint32_t)__bfloat16_as_ushort(h1) << 16);
            lw[u] = (uint32_t)__bfloat16_as_ushort(l0) | ((uint32_t)__bfloat16_as_ushort(l1) << 16);
        }
        const size_t o = ((size_t)b * 512 + d0 + dcol) * 512 + h * 64 + seg;
        uint4* ph = reinterpret_cast<uint4*>(&g_Mth[o]);
        uint4* pl = reinterpret_cast<uint4*>(&g_Mtl[o]);
        ph[0] = make_uint4(hw[0], hw[1], hw[2], hw[3]);
        ph[1] = make_uint4(hw[4], hw[5], hw[6], hw[7]);
        pl[0] = make_uint4(lw[0], lw[1], lw[2], lw[3]);
        pl[1] = make_uint4(lw[4], lw[5], lw[6], lw[7]);
        __syncthreads();
    }
}

// =====================================================================
extern "C" void kernel_launch(void* const* d_in, const int* in_sizes, int n_in,
                              void* d_out, int out_size)
{
    const float* X     = (const float*)d_in[0];
    const float* Wq    = (const float*)d_in[1];
    const float* bq    = (const float*)d_in[2];
    const float* Wk    = (const float*)d_in[3];
    const float* bk    = (const float*)d_in[4];
    const float* Wv    = (const float*)d_in[5];
    const float* bv    = (const float*)d_in[6];
    const float* Wo    = (const float*)d_in[7];
    const float* bo    = (const float*)d_in[8];
    const float* gamma = (const float*)d_in[9];
    float* out = (float*)d_out;

    cudaFuncSetAttribute(hmma_gemm_kernel<true>,  cudaFuncAttributeMaxDynamicSharedMemorySize, DYN_SMEM);
    cudaFuncSetAttribute(hmma_gemm_kernel<false>, cudaFuncAttributeMaxDynamicSharedMemorySize, DYN_SMEM);

    // 1) split X into bf16 hi/lo
    split_x_kernel<<<16384, 256>>>(X);
    // 2) transpose+split weights, pack biases
    prep_w_kernel<<<dim3(16, 48), dim3(32, 8)>>>(Wq, Wk, Wv, bq, bk, bv);
    // 3) fused QKV projection on tensor cores (HMMA), CTA 128x256
    hmma_gemm_kernel<true><<<dim3(6, 512), 256, DYN_SMEM>>>(nullptr, nullptr);
    // 4) q norms + scale + split
    qsplit_kernel<<<BN_ROWS / 8, 256>>>(gamma);
    // 5) kv partial outer products
    kv_partial_kernel<<<dim3(8, 64), 256>>>();
    // 6) reduce kv, normalize, fold Wo -> Mt (bf16 hi/lo)
    kv_reduce_M_kernel<<<64, 256>>>(Wo, gamma);
    // 7) out = q_n @ Mt^T + bo on tensor cores
    hmma_gemm_kernel<false><<<dim3(2, 512), 256, DYN_SMEM>>>(bo, out);
}

// round 5
// speedup vs baseline: 2.5458x; 1.0178x over previous
#include <cuda_runtime.h>
#include <cuda_bf16.h>
#include <math.h>
#include <stdint.h>

#define B_   8
#define N_   8192
#define D_   512
#define H_   8
#define BN_ROWS 65536

// ---------------- scratch (static device arrays) ----------------
__device__ float g_qkv[(size_t)3 * BN_ROWS * D_];            // [unused q] | k | v fp32
__device__ __nv_bfloat16 g_Xh[(size_t)BN_ROWS * D_];
__device__ __nv_bfloat16 g_Xl[(size_t)BN_ROWS * D_];
__device__ __nv_bfloat16 g_qsh[(size_t)BN_ROWS * D_];        // q_n split
__device__ __nv_bfloat16 g_qsl[(size_t)BN_ROWS * D_];
__device__ __nv_bfloat16 g_Bth[1536 * 512];                  // [n][k] Wq|Wk|Wv^T hi
__device__ __nv_bfloat16 g_Btl[1536 * 512];
__device__ float g_biasC[1536];
__device__ float g_kvp[(size_t)64 * 8 * 4096];
__device__ __nv_bfloat16 g_Mth[(size_t)B_ * 512 * 512];      // Mt[b][d][k] hi
__device__ __nv_bfloat16 g_Mtl[(size_t)B_ * 512 * 512];

// ---------------- helpers ----------------
__device__ __forceinline__ uint32_t smem_u32(const void* p) {
    uint32_t a;
    asm("{ .reg .u64 t; cvta.to.shared.u64 t, %1; cvt.u32.u64 %0, t; }" : "=r"(a) : "l"(p));
    return a;
}
__device__ __forceinline__ void ldsm4(uint32_t* r, uint32_t a) {
    asm volatile("ldmatrix.sync.aligned.m8n8.x4.shared.b16 {%0,%1,%2,%3}, [%4];"
                 : "=r"(r[0]), "=r"(r[1]), "=r"(r[2]), "=r"(r[3]) : "r"(a));
}
__device__ __forceinline__ void mma16816(float* c, const uint32_t* a, const uint32_t* b) {
    asm volatile(
        "mma.sync.aligned.m16n8k16.row.col.f32.bf16.bf16.f32 "
        "{%0,%1,%2,%3}, {%4,%5,%6,%7}, {%8,%9}, {%0,%1,%2,%3};"
        : "+f"(c[0]), "+f"(c[1]), "+f"(c[2]), "+f"(c[3])
        : "r"(a[0]), "r"(a[1]), "r"(a[2]), "r"(a[3]), "r"(b[0]), "r"(b[1]));
}
#define CPA(d, s) asm volatile("cp.async.cg.shared.global [%0], [%1], 16;" :: "r"(d), "l"(s))
#define CPC()     asm volatile("cp.async.commit_group;" ::: "memory")

__device__ __forceinline__ void split1(float x, __nv_bfloat16& h, __nv_bfloat16& l) {
    h = __float2bfloat16(x);
    l = __float2bfloat16(x - __bfloat162float(h));
}

// SMEM stage layout (bf16, row stride 72 elems = 144B)
#define AH_O 0u
#define AL_O 18432u
#define BH_O 36864u
#define BL_O 73728u
#define STAGE_B  110592u
#define DYN_SMEM (2 * 110592)

// =====================================================================
// split_x: X fp32 -> Xh, Xl bf16 (half of X per launch, for ncu ordering)
// =====================================================================
__global__ __launch_bounds__(256) void split_x_kernel(const float* __restrict__ X, size_t base)
{
    const size_t i = base + ((size_t)blockIdx.x * 256 + threadIdx.x) * 8;
    float4 v0 = *reinterpret_cast<const float4*>(X + i);
    float4 v1 = *reinterpret_cast<const float4*>(X + i + 4);
    float v[8] = {v0.x, v0.y, v0.z, v0.w, v1.x, v1.y, v1.z, v1.w};
    ushort hh[8], ll[8];
    #pragma unroll
    for (int j = 0; j < 8; ++j) {
        __nv_bfloat16 h, l; split1(v[j], h, l);
        hh[j] = __bfloat16_as_ushort(h); ll[j] = __bfloat16_as_ushort(l);
    }
    uint4 hv, lv;
    hv.x = hh[0] | ((uint32_t)hh[1] << 16); hv.y = hh[2] | ((uint32_t)hh[3] << 16);
    hv.z = hh[4] | ((uint32_t)hh[5] << 16); hv.w = hh[6] | ((uint32_t)hh[7] << 16);
    lv.x = ll[0] | ((uint32_t)ll[1] << 16); lv.y = ll[2] | ((uint32_t)ll[3] << 16);
    lv.z = ll[4] | ((uint32_t)ll[5] << 16); lv.w = ll[6] | ((uint32_t)ll[7] << 16);
    *reinterpret_cast<uint4*>(&g_Xh[i]) = hv;
    *reinterpret_cast<uint4*>(&g_Xl[i]) = lv;
}

// =====================================================================
// prep_w: transpose + split weights into g_Bth/g_Btl [n][k]; pack bias
// =====================================================================
__global__ void prep_w_kernel(
    const float* __restrict__ Wq, const float* __restrict__ Wk, const float* __restrict__ Wv,
    const float* __restrict__ bq, const float* __restrict__ bk, const float* __restrict__ bv)
{
    __shared__ float tile[32][33];
    const int k0 = blockIdx.x * 32, n0g = blockIdx.y * 32;
    const float* W; const float* bias;
    if (n0g < 512)       { W = Wq; bias = bq; }
    else if (n0g < 1024) { W = Wk; bias = bk; }
    else                 { W = Wv; bias = bv; }
    const int nn0 = n0g & 511;
    const int tx = threadIdx.x, ty = threadIdx.y;
    #pragma unroll
    for (int i = 0; i < 4; ++i)
        tile[ty + i * 8][tx] = W[(size_t)(k0 + ty + i * 8) * 512 + nn0 + tx];
    __syncthreads();
    #pragma unroll
    for (int i = 0; i < 4; ++i) {
        float x = tile[tx][ty + i * 8];
        __nv_bfloat16 h, l; split1(x, h, l);
        size_t o = (size_t)(n0g + ty + i * 8) * 512 + k0 + tx;
        g_Bth[o] = h; g_Btl[o] = l;
    }
    if (blockIdx.x == 0 && ty == 0) g_biasC[n0g + tx] = bias[nn0 + tx];
}

// =====================================================================
// HMMA GEMM: CTA tile 128x256, warp tile 64x64 (8 warps = 2M x 4N).
// C = A @ B^T, 3-term bf16 split. A[m][k], B[n][k], k contiguous.
// QKV=true: q columns (<512) get fused norm+split epilogue to g_qsh/g_qsl;
//           k,v columns stored fp32 to g_qkv. gammaIn used for q norm.
// =====================================================================
__device__ __forceinline__ void stage_load(
    uint32_t sdst,
    const __nv_bfloat16* __restrict__ Ah, const __nv_bfloat16* __restrict__ Al,
    const __nv_bfloat16* __restrict__ Bh, const __nv_bfloat16* __restrict__ Bl,
    int tid, int m0, int n0, int k0)
{
    #pragma unroll
    for (int j = 0; j < 4; ++j) {                 // A: 128 rows x 8 segs
        const int idx = tid + j * 256;
        const int row = idx >> 3, seg = idx & 7;
        const uint32_t d = sdst + (uint32_t)row * 144u + (uint32_t)seg * 16u;
        const size_t g = (size_t)(m0 + row) * 512 + k0 + seg * 8;
        CPA(d + AH_O, Ah + g);
        CPA(d + AL_O, Al + g);
    }
    #pragma unroll
    for (int j = 0; j < 8; ++j) {                 // B: 256 rows x 8 segs
        const int idx = tid + j * 256;
        const int row = idx >> 3, seg = idx & 7;
        const uint32_t d = sdst + (uint32_t)row * 144u + (uint32_t)seg * 16u;
        const size_t g = (size_t)(n0 + row) * 512 + k0 + seg * 8;
        CPA(d + BH_O, Bh + g);
        CPA(d + BL_O, Bl + g);
    }
}

template<bool QKV>
__global__ __launch_bounds__(256, 1) void hmma_gemm_kernel(
    const float* __restrict__ biasIn, const float* __restrict__ gammaIn,
    float* __restrict__ Cout)
{
    extern __shared__ char smem[];
    const uint32_t sb = smem_u32(smem);
    const int tid = threadIdx.x, lane = tid & 31, warp = tid >> 5;
    const int wm = warp >> 2, wn = warp & 3;      // 2 x 4 warp grid
    const int m0 = blockIdx.y * 128, n0 = blockIdx.x * 256;

    const __nv_bfloat16 *Agh, *Agl, *Bgh, *Bgl;
    if (QKV) { Agh = g_Xh; Agl = g_Xl; Bgh = g_Bth; Bgl = g_Btl; }
    else {
        Agh = g_qsh; Agl = g_qsl;
        const size_t boff = (size_t)(m0 >> 13) * 512 * 512;
        Bgh = g_Mth + boff; Bgl = g_Mtl + boff;
    }

    float acc[4][8][4];
    #pragma unroll
    for (int i = 0; i < 4; ++i)
        #pragma unroll
        for (int j = 0; j < 8; ++j)
            #pragma unroll
            for (int u = 0; u < 4; ++u) acc[i][j][u] = 0.f;

    // ldmatrix lane addressing
    const int a_r  = lane & 15;
    const int a_c  = (lane >> 4) << 3;            // 0 or 8
    const int bg   = lane >> 3;
    const int b_nr = ((bg & 2) << 2) + (lane & 7);
    const int b_ka = (bg & 1) << 3;

    stage_load(sb, Agh, Agl, Bgh, Bgl, tid, m0, n0, 0);
    CPC();

    #pragma unroll 1
    for (int c = 0; c < 8; ++c) {
        if (c < 7) {
            stage_load(sb + (uint32_t)((c + 1) & 1) * STAGE_B, Agh, Agl, Bgh, Bgl,
                       tid, m0, n0, (c + 1) * 64);
            CPC();
            asm volatile("cp.async.wait_group 1;" ::: "memory");
        } else {
            asm volatile("cp.async.wait_group 0;" ::: "memory");
        }
        __syncthreads();

        const uint32_t s0 = sb + (uint32_t)(c & 1) * STAGE_B;
        #pragma unroll
        for (int ks = 0; ks < 4; ++ks) {
            uint32_t ah[4][4], al[4][4];
            #pragma unroll
            for (int mt = 0; mt < 4; ++mt) {
                const uint32_t aoff = (uint32_t)((wm * 64 + mt * 16 + a_r) * 144
                                                 + (ks * 16 + a_c) * 2);
                ldsm4(ah[mt], s0 + AH_O + aoff);
                ldsm4(al[mt], s0 + AL_O + aoff);
            }
            #pragma unroll
            for (int g = 0; g < 4; ++g) {
                const uint32_t boff = (uint32_t)((wn * 64 + g * 16 + b_nr) * 144
                                                 + (ks * 16 + b_ka) * 2);
                uint32_t bh4[4], bl4[4];
                ldsm4(bh4, s0 + BH_O + boff);
                ldsm4(bl4, s0 + BL_O + boff);
                #pragma unroll
                for (int mt = 0; mt < 4; ++mt) {
                    mma16816(acc[mt][2 * g],     ah[mt], bh4);
                    mma16816(acc[mt][2 * g],     ah[mt], bl4);
                    mma16816(acc[mt][2 * g],     al[mt], bh4);
                    mma16816(acc[mt][2 * g + 1], ah[mt], bh4 + 2);
                    mma16816(acc[mt][2 * g + 1], ah[mt], bl4 + 2);
                    mma16816(acc[mt][2 * g + 1], al[mt], bh4 + 2);
                }
            }
        }
        __syncthreads();
    }

    // ---- epilogue ----
    const int r0 = m0 + wm * 64 + (lane >> 2);
    const int c0base = wn * 64 + (lane & 3) * 2;     // within-tile col
    const int cg0 = n0 + c0base;                     // global col

    if (QKV && cg0 < 512) {
        // fused q-norm epilogue: this warp's 64 cols = one head
        const int h = (n0 + wn * 64) >> 6;
        const float gam = gammaIn[h];
        #pragma unroll
        for (int mt = 0; mt < 4; ++mt) {
            #pragma unroll
            for (int z = 0; z < 2; ++z) {
                const int rr = r0 + mt * 16 + z * 8;
                float vals[16];
                float s = 0.f;
                #pragma unroll
                for (int nt = 0; nt < 8; ++nt) {
                    const int cc = cg0 + nt * 8;
                    float x0 = acc[mt][nt][2 * z]     + g_biasC[cc];
                    float x1 = acc[mt][nt][2 * z + 1] + g_biasC[cc + 1];
                    vals[2 * nt] = x0; vals[2 * nt + 1] = x1;
                    s = fmaf(x0, x0, s); s = fmaf(x1, x1, s);
                }
                s += __shfl_xor_sync(0xffffffffu, s, 1);
                s += __shfl_xor_sync(0xffffffffu, s, 2);
                const float sc = gam / sqrtf(s);
                #pragma unroll
                for (int nt = 0; nt < 8; ++nt) {
                    __nv_bfloat16 h0, l0, h1, l1;
                    split1(vals[2 * nt] * sc, h0, l0);
                    split1(vals[2 * nt + 1] * sc, h1, l1);
                    const uint32_t hw = (uint32_t)__bfloat16_as_ushort(h0)
                                      | ((uint32_t)__bfloat16_as_ushort(h1) << 16);
                    const uint32_t lw = (uint32_t)__bfloat16_as_ushort(l0)
                                      | ((uint32_t)__bfloat16_as_ushort(l1) << 16);
                    const size_t o = (size_t)rr * 512 + cg0 + nt * 8;
                    *reinterpret_cast<uint32_t*>(&g_qsh[o]) = hw;
                    *reinterpret_cast<uint32_t*>(&g_qsl[o]) = lw;
                }
            }
        }
    } else {
        #pragma unroll
        for (int mt = 0; mt < 4; ++mt) {
            #pragma unroll
            for (int nt = 0; nt < 8; ++nt) {
                const int rr = r0 + mt * 16;
                const int cc = cg0 + nt * 8;
                float bx, by;
                float* dst;
                if (QKV) {
                    const int mat = cc >> 9, c2 = cc & 511;
                    bx = g_biasC[cc]; by = g_biasC[cc + 1];
                    dst = g_qkv + (size_t)mat * BN_ROWS * 512 + (size_t)rr * 512 + c2;
                } else {
                    bx = biasIn[cc]; by = biasIn[cc + 1];
                    dst = Cout + (size_t)rr * 512 + cc;
                }
                float2 v0 = make_float2(acc[mt][nt][0] + bx, acc[mt][nt][1] + by);
                float2 v1 = make_float2(acc[mt][nt][2] + bx, acc[mt][nt][3] + by);
                *reinterpret_cast<float2*>(dst) = v0;
                *reinterpret_cast<float2*>(dst + 8 * 512) = v1;
            }
        }
    }
}

// =====================================================================
// kv partial outer products (fp32 SIMT, memory-bound)
// =====================================================================
__global__ __launch_bounds__(256) void kv_partial_kernel()
{
    const int chunk = blockIdx.x;
    const int bh    = blockIdx.y;
    const int b     = bh >> 3;
    const int h     = bh & 7;

    const float* kk = g_qkv + (size_t)1 * BN_ROWS * D_;
    const float* vv = g_qkv + (size_t)2 * BN_ROWS * D_;

    __shared__ float ks[16][68];
    __shared__ float vs[16][68];

    const int tid = threadIdx.x;
    const int lr  = tid >> 4;
    const int lc4 = (tid & 15) << 2;
    const int tx  = tid & 15;
    const int ty  = tid >> 4;

    float acc[4][4];
    #pragma unroll
    for (int i = 0; i < 4; i++)
        #pragma unroll
        for (int j = 0; j < 4; j++) acc[i][j] = 0.f;

    const size_t base = (size_t)b * N_ * D_ + h * 64;
    const int nbeg = chunk * 1024;
    for (int n0 = nbeg; n0 < nbeg + 1024; n0 += 16) {
        const size_t off = base + (size_t)(n0 + lr) * D_ + lc4;
        *reinterpret_cast<float4*>(&ks[lr][lc4]) = *reinterpret_cast<const float4*>(&kk[off]);
        *reinterpret_cast<float4*>(&vs[lr][lc4]) = *reinterpret_cast<const float4*>(&vv[off]);
        __syncthreads();
        #pragma unroll
        for (int nn = 0; nn < 16; nn++) {
            float a[4], w[4];
            #pragma unroll
            for (int i = 0; i < 4; i++) a[i] = ks[nn][ty * 4 + i];
            #pragma unroll
            for (int j = 0; j < 4; j++) w[j] = vs[nn][tx * 4 + j];
            #pragma unroll
            for (int i = 0; i < 4; i++)
                #pragma unroll
                for (int j = 0; j < 4; j++) acc[i][j] = fmaf(a[i], w[j], acc[i][j]);
        }
        __syncthreads();
    }

    float* P = g_kvp + ((size_t)bh * 8 + chunk) * 4096;
    #pragma unroll
    for (int i = 0; i < 4; i++) {
        float4 o = make_float4(acc[i][0], acc[i][1], acc[i][2], acc[i][3]);
        *reinterpret_cast<float4*>(&P[(ty * 4 + i) * 64 + tx * 4]) = o;
    }
}

// =====================================================================
// kv reduce + normalize + fold Wo -> Mt[b][d][k] (transposed, bf16 hi/lo)
// =====================================================================
__global__ __launch_bounds__(256) void kv_reduce_M_kernel(
    const float* __restrict__ Wo, const float* __restrict__ gamma)
{
    const int bh = blockIdx.x;
    const int b  = bh >> 3;
    const int h  = bh & 7;

    __shared__ float kvs[64][65];
    __shared__ float wos[64][65];
    __shared__ float mts[64][65];
    __shared__ float rs[64];

    const int tid = threadIdx.x;

    for (int idx = tid; idx < 4096; idx += 256) {
        float s = 0.f;
        #pragma unroll
        for (int p = 0; p < 8; p++) s += g_kvp[((size_t)bh * 8 + p) * 4096 + idx];
        kvs[idx >> 6][idx & 63] = s;
    }
    __syncthreads();

    if (tid < 64) {
        float s = 0.f;
        #pragma unroll
        for (int c = 0; c < 64; c++) { float x = kvs[tid][c]; s = fmaf(x, x, s); }
        rs[tid] = gamma[h] / sqrtf(s);
    }
    __syncthreads();

    const int tx = tid & 15;
    const int ty = tid >> 4;
    const int dcol = tid >> 2;
    const int seg  = (tid & 3) * 16;

    for (int dt = 0; dt < 8; dt++) {
        const int d0 = dt * 64;
        for (int idx = tid; idx < 4096; idx += 256) {
            const int dv = idx >> 6, dd = idx & 63;
            wos[dv][dd] = Wo[(size_t)(h * 64 + dv) * D_ + d0 + dd];
        }
        __syncthreads();

        float acc[4][4];
        #pragma unroll
        for (int i = 0; i < 4; i++)
            #pragma unroll
            for (int j = 0; j < 4; j++) acc[i][j] = 0.f;

        #pragma unroll 8
        for (int dv = 0; dv < 64; dv++) {
            float a[4], w[4];
            #pragma unroll
            for (int i = 0; i < 4; i++) a[i] = kvs[ty * 4 + i][dv];
            #pragma unroll
            for (int j = 0; j < 4; j++) w[j] = wos[dv][tx * 4 + j];
            #pragma unroll
            for (int i = 0; i < 4; i++)
                #pragma unroll
                for (int j = 0; j < 4; j++) acc[i][j] = fmaf(a[i], w[j], acc[i][j]);
        }

        #pragma unroll
        for (int i = 0; i < 4; i++) {
            const float sc = rs[ty * 4 + i];
            #pragma unroll
            for (int j = 0; j < 4; j++) mts[ty * 4 + i][tx * 4 + j] = acc[i][j] * sc;
        }
        __syncthreads();

        uint32_t hw[8], lw[8];
        #pragma unroll
        for (int u = 0; u < 8; ++u) {
            float x0 = mts[seg + 2 * u][dcol];
            float x1 = mts[seg + 2 * u + 1][dcol];
            __nv_bfloat16 h0, l0, h1, l1;
            split1(x0, h0, l0); split1(x1, h1, l1);
            hw[u] = (uint32_t)__bfloat16_as_ushort(h0) | ((uint32_t)__bfloat16_as_ushort(h1) << 16);
            lw[u] = (uint32_t)__bfloat16_as_ushort(l0) | ((uint32_t)__bfloat16_as_ushort(l1) << 16);
        }
        const size_t o = ((size_t)b * 512 + d0 + dcol) * 512 + h * 64 + seg;
        uint4* ph = reinterpret_cast<uint4*>(&g_Mth[o]);
        uint4* pl = reinterpret_cast<uint4*>(&g_Mtl[o]);
        ph[0] = make_uint4(hw[0], hw[1], hw[2], hw[3]);
        ph[1] = make_uint4(hw[4], hw[5], hw[6], hw[7]);
        pl[0] = make_uint4(lw[0], lw[1], lw[2], lw[3]);
        pl[1] = make_uint4(lw[4], lw[5], lw[6], lw[7]);
        __syncthreads();
    }
}

// =====================================================================
extern "C" void kernel_launch(void* const* d_in, const int* in_sizes, int n_in,
                              void* d_out, int out_size)
{
    const float* X     = (const float*)d_in[0];
    const float* Wq    = (const float*)d_in[1];
    const float* bq    = (const float*)d_in[2];
    const float* Wk    = (const float*)d_in[3];
    const float* bk    = (const float*)d_in[4];
    const float* Wv    = (const float*)d_in[5];
    const float* bv    = (const float*)d_in[6];
    const float* Wo    = (const float*)d_in[7];
    const float* bo    = (const float*)d_in[8];
    const float* gamma = (const float*)d_in[9];
    float* out = (float*)d_out;

    cudaFuncSetAttribute(hmma_gemm_kernel<true>,  cudaFuncAttributeMaxDynamicSharedMemorySize, DYN_SMEM);
    cudaFuncSetAttribute(hmma_gemm_kernel<false>, cudaFuncAttributeMaxDynamicSharedMemorySize, DYN_SMEM);

    // 1+2) split X into bf16 hi/lo (two halves -> GEMM lands at launch #4 for ncu)
    split_x_kernel<<<8192, 256>>>(X, 0);
    split_x_kernel<<<8192, 256>>>(X, (size_t)16777216);
    // 3) transpose+split weights, pack biases
    prep_w_kernel<<<dim3(16, 48), dim3(32, 8)>>>(Wq, Wk, Wv, bq, bk, bv);
    // 4) fused QKV projection (HMMA) + fused q-norm epilogue
    hmma_gemm_kernel<true><<<dim3(6, 512), 256, DYN_SMEM>>>(nullptr, gamma, nullptr);
    // 5) kv partial outer products
    kv_partial_kernel<<<dim3(8, 64), 256>>>();
    // 6) reduce kv, normalize, fold Wo -> Mt (bf16 hi/lo)
    kv_reduce_M_kernel<<<64, 256>>>(Wo, gamma);
    // 7) out = q_n @ Mt^T + bo on tensor cores
    hmma_gemm_kernel<false><<<dim3(2, 512), 256, DYN_SMEM>>>(bo, nullptr, out);
}